// round 1
// baseline (speedup 1.0000x reference)
#include <cuda_runtime.h>
#include <cuda_bf16.h>

// Problem constants (fixed by setup_inputs)
#define NB   4          // batch
#define SS   4096       // sequence
#define EE   1024       // embed
#define HH   16         // heads
#define DD   64         // head dim
#define EPSF 1e-3f

#define M_TOTAL (NB*SS)    // 16384

// Scratch (device globals: allocation-free)
__device__ float g_q[NB*SS*EE];     // 64 MB
__device__ float g_k[NB*SS*EE];     // 64 MB
__device__ float g_v[NB*SS*EE];     // 64 MB
__device__ float g_kv[NB*HH*DD*DD]; // 1 MB
__device__ float g_ksum[NB*HH*DD];  // 16 KB

// ---------------------------------------------------------------------------
// Kernel 1: fused QKV projection GEMM.
//   out[m, n] = sum_k x[m,k] * W[n,k] + bias[n]   (torch Linear: x @ W.T + b)
//   z = 0 -> Q (relu+eps), 1 -> K (relu+eps), 2 -> V (plain)
// Tiles: BM=BN=128, BK=16, 256 threads, 8x8 per-thread micro-tile.
// ---------------------------------------------------------------------------
#define BM 128
#define BN 128
#define BK 16
#define LDP 132   // padded shared leading dim (132 % 4 == 0 for float4 align)

__global__ __launch_bounds__(256, 1) void qkv_gemm(
    const float* __restrict__ x,
    const float* __restrict__ wq, const float* __restrict__ bq,
    const float* __restrict__ wk, const float* __restrict__ bk,
    const float* __restrict__ wv, const float* __restrict__ bv)
{
    __shared__ float As[BK][LDP];
    __shared__ float Bs[BK][LDP];

    const float* w;
    const float* bias;
    float* out;
    bool relu;
    int z = blockIdx.z;
    if (z == 0)      { w = wq; bias = bq; out = g_q; relu = true;  }
    else if (z == 1) { w = wk; bias = bk; out = g_k; relu = true;  }
    else             { w = wv; bias = bv; out = g_v; relu = false; }

    const int m0 = blockIdx.y * BM;
    const int n0 = blockIdx.x * BN;
    const int tid = threadIdx.x;
    const int tm = tid >> 4;     // 0..15
    const int tn = tid & 15;     // 0..15

    float acc[8][8];
#pragma unroll
    for (int i = 0; i < 8; i++)
#pragma unroll
        for (int j = 0; j < 8; j++) acc[i][j] = 0.f;

    for (int k0 = 0; k0 < EE; k0 += BK) {
        // Load A tile (128 x 16) transposed into As[k][m]. 512 float4 loads.
#pragma unroll
        for (int it = 0; it < 2; it++) {
            int f = tid + it * 256;
            int row = f >> 2;            // 0..127
            int c4 = (f & 3) * 4;        // 0,4,8,12
            float4 v = *(const float4*)&x[(size_t)(m0 + row) * EE + k0 + c4];
            As[c4 + 0][row] = v.x;
            As[c4 + 1][row] = v.y;
            As[c4 + 2][row] = v.z;
            As[c4 + 3][row] = v.w;
        }
        // Load B tile (128 x 16) transposed into Bs[k][n].
#pragma unroll
        for (int it = 0; it < 2; it++) {
            int f = tid + it * 256;
            int row = f >> 2;
            int c4 = (f & 3) * 4;
            float4 v = *(const float4*)&w[(size_t)(n0 + row) * EE + k0 + c4];
            Bs[c4 + 0][row] = v.x;
            Bs[c4 + 1][row] = v.y;
            Bs[c4 + 2][row] = v.z;
            Bs[c4 + 3][row] = v.w;
        }
        __syncthreads();

#pragma unroll
        for (int kk = 0; kk < BK; kk++) {
            float a[8], b[8];
            *(float4*)&a[0] = *(const float4*)&As[kk][tm * 8];
            *(float4*)&a[4] = *(const float4*)&As[kk][tm * 8 + 4];
            *(float4*)&b[0] = *(const float4*)&Bs[kk][tn * 8];
            *(float4*)&b[4] = *(const float4*)&Bs[kk][tn * 8 + 4];
#pragma unroll
            for (int i = 0; i < 8; i++)
#pragma unroll
                for (int j = 0; j < 8; j++)
                    acc[i][j] += a[i] * b[j];
        }
        __syncthreads();
    }

    // Epilogue: bias (+ relu + eps), write back as 2 float4 per row.
#pragma unroll
    for (int i = 0; i < 8; i++) {
        int m = m0 + tm * 8 + i;
        float r[8];
#pragma unroll
        for (int j = 0; j < 8; j++) {
            int n = n0 + tn * 8 + j;
            float v = acc[i][j] + bias[n];
            if (relu) v = fmaxf(v, 0.f) + EPSF;
            r[j] = v;
        }
        float* op = &out[(size_t)m * EE + n0 + tn * 8];
        *(float4*)&op[0] = *(const float4*)&r[0];
        *(float4*)&op[4] = *(const float4*)&r[4];
    }
}

// ---------------------------------------------------------------------------
// Kernel 0: zero kv / ksum scratch
// ---------------------------------------------------------------------------
__global__ void zero_scratch()
{
    int i = blockIdx.x * blockDim.x + threadIdx.x;
    if (i < NB * HH * DD * DD) g_kv[i] = 0.f;
    if (i < NB * HH * DD) g_ksum[i] = 0.f;
}

// ---------------------------------------------------------------------------
// Kernel 2: per-(n,h) kv = K^T V (64x64) and ksum = sum_s K[s,:].
// Grid: (64 heads, 8 S-splits). Each block handles 512 s rows, atomically
// accumulates into g_kv/g_ksum.
// ---------------------------------------------------------------------------
#define SPLITS 8
#define SCHUNK 64

__global__ __launch_bounds__(256, 1) void kv_ksum_kernel()
{
    const int nh = blockIdx.x;           // 0..63
    const int split = blockIdx.y;        // 0..7
    const int n = nh >> 4, h = nh & 15;
    const float* kb = g_k + (size_t)n * SS * EE + h * DD;
    const float* vb = g_v + (size_t)n * SS * EE + h * DD;

    __shared__ float Ks[SCHUNK][DD + 4];
    __shared__ float Vs[SCHUNK][DD + 4];

    const int tid = threadIdx.x;
    const int ti = tid >> 4;   // 0..15  (d group)
    const int tj = tid & 15;   // 0..15  (e group)

    float acc[4][4];
#pragma unroll
    for (int a = 0; a < 4; a++)
#pragma unroll
        for (int b = 0; b < 4; b++) acc[a][b] = 0.f;
    float ksl = 0.f;

    const int sbeg = split * (SS / SPLITS);
    const int send = sbeg + (SS / SPLITS);

    for (int s0 = sbeg; s0 < send; s0 += SCHUNK) {
        // load 64x64 K and V chunks (each: 1024 float4, 4 per thread)
#pragma unroll
        for (int it = 0; it < 4; it++) {
            int f = tid + it * 256;
            int row = f >> 4;            // 0..63
            int c4 = (f & 15) * 4;       // 0..60
            float4 kv4 = *(const float4*)&kb[(size_t)(s0 + row) * EE + c4];
            Ks[row][c4 + 0] = kv4.x; Ks[row][c4 + 1] = kv4.y;
            Ks[row][c4 + 2] = kv4.z; Ks[row][c4 + 3] = kv4.w;
            float4 vv4 = *(const float4*)&vb[(size_t)(s0 + row) * EE + c4];
            Vs[row][c4 + 0] = vv4.x; Vs[row][c4 + 1] = vv4.y;
            Vs[row][c4 + 2] = vv4.z; Vs[row][c4 + 3] = vv4.w;
        }
        __syncthreads();

#pragma unroll 4
        for (int s = 0; s < SCHUNK; s++) {
            float kf[4], vf[4];
            *(float4*)&kf[0] = *(const float4*)&Ks[s][ti * 4];
            *(float4*)&vf[0] = *(const float4*)&Vs[s][tj * 4];
#pragma unroll
            for (int a = 0; a < 4; a++)
#pragma unroll
                for (int b = 0; b < 4; b++)
                    acc[a][b] += kf[a] * vf[b];
        }
        if (tid < DD) {
#pragma unroll 8
            for (int s = 0; s < SCHUNK; s++) ksl += Ks[s][tid];
        }
        __syncthreads();
    }

#pragma unroll
    for (int a = 0; a < 4; a++)
#pragma unroll
        for (int b = 0; b < 4; b++)
            atomicAdd(&g_kv[(size_t)nh * DD * DD + (ti * 4 + a) * DD + tj * 4 + b],
                      acc[a][b]);
    if (tid < DD) atomicAdd(&g_ksum[nh * DD + tid], ksl);
}

// ---------------------------------------------------------------------------
// Kernel 3: out[n,h,s,e] = (q[s,:] @ kv) / (q[s,:] . ksum)
// Grid: (64 heads, 128 s-tiles of 32). 256 threads: 32 rows x 8 e-groups.
// ---------------------------------------------------------------------------
__global__ __launch_bounds__(256, 1) void out_kernel(float* __restrict__ out)
{
    const int nh = blockIdx.x;
    const int s0 = blockIdx.y * 32;
    const int n = nh >> 4, h = nh & 15;

    __shared__ float kvs[DD][DD + 4];
    __shared__ float kss[DD];
    __shared__ float qs[32][DD + 4];

    const int tid = threadIdx.x;

    for (int idx = tid; idx < DD * DD; idx += 256)
        kvs[idx >> 6][idx & 63] = g_kv[(size_t)nh * DD * DD + idx];
    if (tid < DD) kss[tid] = g_ksum[nh * DD + tid];

    const float* qb = g_q + (size_t)n * SS * EE + h * DD;
    for (int idx = tid; idx < 32 * DD; idx += 256) {
        int r = idx >> 6, c = idx & 63;
        qs[r][c] = qb[(size_t)(s0 + r) * EE + c];
    }
    __syncthreads();

    const int r = tid >> 3;        // 0..31 (s row)
    const int e0 = (tid & 7) * 8;  // e group

    float diag = 0.f;
#pragma unroll
    for (int c = 0; c < DD; c++) diag += qs[r][c] * kss[c];

    float o[8];
#pragma unroll
    for (int j = 0; j < 8; j++) o[j] = 0.f;
#pragma unroll
    for (int c = 0; c < DD; c++) {
        float qv = qs[r][c];
#pragma unroll
        for (int j = 0; j < 8; j++)
            o[j] += qv * kvs[c][e0 + j];
    }

    float inv = 1.0f / diag;
    float res[8];
#pragma unroll
    for (int j = 0; j < 8; j++) res[j] = o[j] * inv;

    float* op = &out[((size_t)nh * SS + s0 + r) * DD + e0];
    *(float4*)&op[0] = *(const float4*)&res[0];
    *(float4*)&op[4] = *(const float4*)&res[4];
}

// ---------------------------------------------------------------------------
// Launch
// ---------------------------------------------------------------------------
extern "C" void kernel_launch(void* const* d_in, const int* in_sizes, int n_in,
                              void* d_out, int out_size)
{
    const float* x  = (const float*)d_in[0];
    const float* wq = (const float*)d_in[1];
    const float* bq = (const float*)d_in[2];
    const float* wk = (const float*)d_in[3];
    const float* bk = (const float*)d_in[4];
    const float* wv = (const float*)d_in[5];
    const float* bv = (const float*)d_in[6];
    float* out = (float*)d_out;

    zero_scratch<<<(NB * HH * DD * DD + 255) / 256, 256>>>();

    dim3 ggrid(EE / BN, M_TOTAL / BM, 3);   // (8, 128, 3)
    qkv_gemm<<<ggrid, 256>>>(x, wq, bq, wk, bk, wv, bv);

    dim3 kvgrid(NB * HH, SPLITS);           // (64, 8)
    kv_ksum_kernel<<<kvgrid, 256>>>();

    dim3 ogrid(NB * HH, SS / 32);           // (64, 128)
    out_kernel<<<ogrid, 256>>>(out);
}

// round 5
// speedup vs baseline: 2.6342x; 2.6342x over previous
#include <cuda_runtime.h>
#include <cuda_bf16.h>
#include <cstdint>

// Problem constants (fixed by setup_inputs)
#define NB   4
#define SS   4096
#define EE   1024
#define HH   16
#define DD   64
#define EPSF 1e-3f

#define M_TOTAL (NB*SS)    // 16384

// Scratch (device globals: allocation-free)
__device__ float g_q[NB*SS*EE];     // 64 MB
__device__ float g_k[NB*SS*EE];     // 64 MB
__device__ float g_v[NB*SS*EE];     // 64 MB
__device__ float g_kv[NB*HH*DD*DD]; // 1 MB
__device__ float g_ksum[NB*HH*DD];  // 16 KB

// bf16 hi/lo split copies (16B aligned for cp.async)
__device__ __align__(16) __nv_bfloat16 g_xhi[M_TOTAL*EE];   // 32 MB
__device__ __align__(16) __nv_bfloat16 g_xlo[M_TOTAL*EE];   // 32 MB
__device__ __align__(16) __nv_bfloat16 g_whi[3*EE*EE];      // 6 MB
__device__ __align__(16) __nv_bfloat16 g_wlo[3*EE*EE];      // 6 MB

#define SWZ(x) ((x) ^ (((x) >> 3) & 0x70))

// ---------------------------------------------------------------------------
// PTX helpers (portable ISA only: ldmatrix / mma.sync / cp.async)
// ---------------------------------------------------------------------------
__device__ __forceinline__ uint32_t smem_u32(const void* p) {
    uint32_t a;
    asm("{ .reg .u64 t; cvta.to.shared.u64 t, %1; cvt.u32.u64 %0, t; }"
        : "=r"(a) : "l"(p));
    return a;
}
__device__ __forceinline__ void cpa16(uint32_t dst, const void* src) {
    asm volatile("cp.async.cg.shared.global [%0], [%1], 16;"
                 :: "r"(dst), "l"(src) : "memory");
}
__device__ __forceinline__ void cpa_commit() {
    asm volatile("cp.async.commit_group;" ::: "memory");
}
template <int N>
__device__ __forceinline__ void cpa_wait() {
    asm volatile("cp.async.wait_group %0;" :: "n"(N) : "memory");
}
__device__ __forceinline__ void ldsm4(uint32_t* r, uint32_t addr) {
    asm volatile("ldmatrix.sync.aligned.m8n8.x4.shared.b16 {%0,%1,%2,%3}, [%4];"
                 : "=r"(r[0]), "=r"(r[1]), "=r"(r[2]), "=r"(r[3]) : "r"(addr));
}
__device__ __forceinline__ void ldsm2(uint32_t* r, uint32_t addr) {
    asm volatile("ldmatrix.sync.aligned.m8n8.x2.shared.b16 {%0,%1}, [%2];"
                 : "=r"(r[0]), "=r"(r[1]) : "r"(addr));
}
__device__ __forceinline__ void mma_bf16(float* d, const uint32_t* a, const uint32_t* b) {
    asm volatile("mma.sync.aligned.m16n8k16.row.col.f32.bf16.bf16.f32 "
                 "{%0,%1,%2,%3}, {%4,%5,%6,%7}, {%8,%9}, {%0,%1,%2,%3};"
                 : "+f"(d[0]), "+f"(d[1]), "+f"(d[2]), "+f"(d[3])
                 : "r"(a[0]), "r"(a[1]), "r"(a[2]), "r"(a[3]),
                   "r"(b[0]), "r"(b[1]));
}

// ---------------------------------------------------------------------------
// Kernel A: split fp32 -> bf16 hi/lo.  which: 0 -> x, 1..3 -> w slot
// ---------------------------------------------------------------------------
__global__ void convert_split(const float* __restrict__ src, int which, int n4)
{
    int i = blockIdx.x * blockDim.x + threadIdx.x;
    if (i >= n4) return;
    __nv_bfloat16* hi;
    __nv_bfloat16* lo;
    if (which == 0) { hi = g_xhi; lo = g_xlo; }
    else {
        hi = g_whi + (size_t)(which - 1) * EE * EE;
        lo = g_wlo + (size_t)(which - 1) * EE * EE;
    }
    float4 v = ((const float4*)src)[i];
    __nv_bfloat162 h01 = __floats2bfloat162_rn(v.x, v.y);
    __nv_bfloat162 h23 = __floats2bfloat162_rn(v.z, v.w);
    __nv_bfloat162 l01 = __floats2bfloat162_rn(v.x - __bfloat162float(h01.x),
                                               v.y - __bfloat162float(h01.y));
    __nv_bfloat162 l23 = __floats2bfloat162_rn(v.z - __bfloat162float(h23.x),
                                               v.w - __bfloat162float(h23.y));
    ((uint2*)hi)[i] = make_uint2(*(uint32_t*)&h01, *(uint32_t*)&h23);
    ((uint2*)lo)[i] = make_uint2(*(uint32_t*)&l01, *(uint32_t*)&l23);
}

// ---------------------------------------------------------------------------
// Kernel B: fused QKV projection with mma.sync bf16 3-term split.
//   out[m,n] = sum_k x[m,k] * W[n,k] + bias[n]
// Tile 128x128, BK=64 (128B SW128 rows), 3-stage cp.async pipeline, 8 warps
// in 2x4 layout (warp tile 64x32).
// ---------------------------------------------------------------------------
#define STAGES 3
#define STAGE_BYTES 65536       // Ahi/Alo/Bhi/Blo, 16KB each
#define SM_GEMM_TOTAL (STAGES * STAGE_BYTES)   // 196608

__global__ __launch_bounds__(256, 1) void qkv_gemm_mma(
    const float* __restrict__ bq, const float* __restrict__ bk,
    const float* __restrict__ bv)
{
    extern __shared__ __align__(1024) char smarr[];
    const uint32_t smb = smem_u32(smarr);
    const int tid = threadIdx.x;
    const int lane = tid & 31;
    const int wid = tid >> 5;
    const int wm = wid & 1;          // 0..1
    const int wn = wid >> 1;         // 0..3
    const int z = blockIdx.z;

    const float* bias = (z == 0) ? bq : (z == 1) ? bk : bv;
    float* outp = (z == 0) ? g_q : (z == 1) ? g_k : g_v;
    const bool relu = (z != 2);
    const __nv_bfloat16* Bhi = g_whi + (size_t)z * EE * EE;
    const __nv_bfloat16* Blo = g_wlo + (size_t)z * EE * EE;
    const int m0 = blockIdx.y * 128;
    const int n0 = blockIdx.x * 128;

    float acc[4][4][4];
#pragma unroll
    for (int i = 0; i < 4; i++)
#pragma unroll
        for (int j = 0; j < 4; j++)
#pragma unroll
            for (int q = 0; q < 4; q++) acc[i][j][q] = 0.f;

    auto load_stage = [&](int s, int kt) {
        const int k0 = kt * 64;
        const uint32_t base = smb + s * STAGE_BYTES;
#pragma unroll
        for (int it = 0; it < 4; it++) {
            int f = tid + it * 256;
            int row = f >> 3;            // 0..127
            int c8 = (f & 7) * 8;        // element col (bf16)
            uint32_t sw = SWZ((uint32_t)(row * 128 + c8 * 2));
            size_t ga = (size_t)(m0 + row) * EE + k0 + c8;
            size_t gb = (size_t)(n0 + row) * EE + k0 + c8;
            cpa16(base + 0     + sw, g_xhi + ga);
            cpa16(base + 16384 + sw, g_xlo + ga);
            cpa16(base + 32768 + sw, Bhi + gb);
            cpa16(base + 49152 + sw, Blo + gb);
        }
    };

    load_stage(0, 0); cpa_commit();
    load_stage(1, 1); cpa_commit();

    for (int kt = 0; kt < 16; kt++) {
        cpa_wait<STAGES - 2>();
        __syncthreads();

        if (kt + STAGES - 1 < 16) load_stage((kt + STAGES - 1) % STAGES, kt + STAGES - 1);
        cpa_commit();

        const uint32_t sb = smb + (kt % STAGES) * STAGE_BYTES;
#pragma unroll
        for (int k16 = 0; k16 < 4; k16++) {
            const int koff = k16 * 32;   // bytes
            uint32_t ahi[4][4], alo[4][4], bhiF[4][2], bloF[4][2];
#pragma unroll
            for (int i = 0; i < 4; i++) {
                int mr = wm * 64 + i * 16 + (lane & 15);
                uint32_t off = SWZ((uint32_t)(mr * 128 + koff + ((lane >> 4) << 4)));
                ldsm4(ahi[i], sb + 0 + off);
                ldsm4(alo[i], sb + 16384 + off);
            }
#pragma unroll
            for (int j = 0; j < 4; j++) {
                int nr = wn * 32 + j * 8 + (lane & 7);
                uint32_t off = SWZ((uint32_t)(nr * 128 + koff + (((lane >> 3) & 1) << 4)));
                ldsm2(bhiF[j], sb + 32768 + off);
                ldsm2(bloF[j], sb + 49152 + off);
            }
#pragma unroll
            for (int i = 0; i < 4; i++)
#pragma unroll
                for (int j = 0; j < 4; j++) {
                    mma_bf16(acc[i][j], ahi[i], bhiF[j]);
                    mma_bf16(acc[i][j], ahi[i], bloF[j]);
                    mma_bf16(acc[i][j], alo[i], bhiF[j]);
                }
        }
        __syncthreads();
    }

    // Epilogue: bias + optional relu+eps, write fp32
    const int g = lane >> 2;     // 0..7 (row in tile)
    const int tg = lane & 3;     // 0..3 (col pair)
#pragma unroll
    for (int i = 0; i < 4; i++) {
        int mbase = m0 + wm * 64 + i * 16 + g;
#pragma unroll
        for (int j = 0; j < 4; j++) {
            int n = n0 + wn * 32 + j * 8 + tg * 2;
            float b0 = __ldg(&bias[n]), b1 = __ldg(&bias[n + 1]);
            float v0 = acc[i][j][0] + b0, v1 = acc[i][j][1] + b1;
            float v2 = acc[i][j][2] + b0, v3 = acc[i][j][3] + b1;
            if (relu) {
                v0 = fmaxf(v0, 0.f) + EPSF; v1 = fmaxf(v1, 0.f) + EPSF;
                v2 = fmaxf(v2, 0.f) + EPSF; v3 = fmaxf(v3, 0.f) + EPSF;
            }
            *(float2*)&outp[(size_t)mbase * EE + n] = make_float2(v0, v1);
            *(float2*)&outp[(size_t)(mbase + 8) * EE + n] = make_float2(v2, v3);
        }
    }
}

// ---------------------------------------------------------------------------
// Kernel 0: zero kv / ksum scratch
// ---------------------------------------------------------------------------
__global__ void zero_scratch()
{
    int i = blockIdx.x * blockDim.x + threadIdx.x;
    if (i < NB * HH * DD * DD) g_kv[i] = 0.f;
    if (i < NB * HH * DD) g_ksum[i] = 0.f;
}

// ---------------------------------------------------------------------------
// Kernel 2: per-(n,h) kv = K^T V (64x64) and ksum = sum_s K[s,:].
// ---------------------------------------------------------------------------
#define SPLITS 8
#define SCHUNK 64

__global__ __launch_bounds__(256, 1) void kv_ksum_kernel()
{
    const int nh = blockIdx.x;
    const int split = blockIdx.y;
    const int n = nh >> 4, h = nh & 15;
    const float* kb = g_k + (size_t)n * SS * EE + h * DD;
    const float* vb = g_v + (size_t)n * SS * EE + h * DD;

    __shared__ float Ks[SCHUNK][DD + 4];
    __shared__ float Vs[SCHUNK][DD + 4];

    const int tid = threadIdx.x;
    const int ti = tid >> 4;
    const int tj = tid & 15;

    float acc[4][4];
#pragma unroll
    for (int a = 0; a < 4; a++)
#pragma unroll
        for (int b = 0; b < 4; b++) acc[a][b] = 0.f;
    float ksl = 0.f;

    const int sbeg = split * (SS / SPLITS);
    const int send = sbeg + (SS / SPLITS);

    for (int s0 = sbeg; s0 < send; s0 += SCHUNK) {
#pragma unroll
        for (int it = 0; it < 4; it++) {
            int f = tid + it * 256;
            int row = f >> 4;
            int c4 = (f & 15) * 4;
            float4 kv4 = *(const float4*)&kb[(size_t)(s0 + row) * EE + c4];
            Ks[row][c4 + 0] = kv4.x; Ks[row][c4 + 1] = kv4.y;
            Ks[row][c4 + 2] = kv4.z; Ks[row][c4 + 3] = kv4.w;
            float4 vv4 = *(const float4*)&vb[(size_t)(s0 + row) * EE + c4];
            Vs[row][c4 + 0] = vv4.x; Vs[row][c4 + 1] = vv4.y;
            Vs[row][c4 + 2] = vv4.z; Vs[row][c4 + 3] = vv4.w;
        }
        __syncthreads();

#pragma unroll 4
        for (int s = 0; s < SCHUNK; s++) {
            float kf[4], vf[4];
            *(float4*)&kf[0] = *(const float4*)&Ks[s][ti * 4];
            *(float4*)&vf[0] = *(const float4*)&Vs[s][tj * 4];
#pragma unroll
            for (int a = 0; a < 4; a++)
#pragma unroll
                for (int b = 0; b < 4; b++)
                    acc[a][b] += kf[a] * vf[b];
        }
        if (tid < DD) {
#pragma unroll 8
            for (int s = 0; s < SCHUNK; s++) ksl += Ks[s][tid];
        }
        __syncthreads();
    }

#pragma unroll
    for (int a = 0; a < 4; a++)
#pragma unroll
        for (int b = 0; b < 4; b++)
            atomicAdd(&g_kv[(size_t)nh * DD * DD + (ti * 4 + a) * DD + tj * 4 + b],
                      acc[a][b]);
    if (tid < DD) atomicAdd(&g_ksum[nh * DD + tid], ksl);
}

// ---------------------------------------------------------------------------
// Kernel 3: out[n,h,s,e] = (q[s,:] @ kv) / (q[s,:] . ksum)
// ---------------------------------------------------------------------------
__global__ __launch_bounds__(256, 1) void out_kernel(float* __restrict__ out)
{
    const int nh = blockIdx.x;
    const int s0 = blockIdx.y * 64;
    const int n = nh >> 4, h = nh & 15;

    __shared__ float kvs[DD][72];
    __shared__ float qs[64][72];
    __shared__ float kss[DD];

    const int tid = threadIdx.x;

    // kv tile: 64x64 = 1024 float4 -> 4 per thread
#pragma unroll
    for (int it = 0; it < 4; it++) {
        int f = tid + it * 256;
        int row = f >> 4;            // 0..63
        int c4 = (f & 15) * 4;       // 0..60
        float4 v = *(const float4*)&g_kv[(size_t)nh * DD * DD + row * DD + c4];
        *(float4*)&kvs[row][c4] = v;
    }
    if (tid < DD) kss[tid] = g_ksum[nh * DD + tid];

    const float* qb = g_q + (size_t)n * SS * EE + h * DD;
#pragma unroll
    for (int it = 0; it < 4; it++) {
        int f = tid + it * 256;
        int row = f >> 4, c4 = (f & 15) * 4;
        float4 v = *(const float4*)&qb[(size_t)(s0 + row) * EE + c4];
        *(float4*)&qs[row][c4] = v;
    }
    __syncthreads();

    const int r = tid >> 3;
    const int e0 = (tid & 7) * 8;

    float acc0[8], acc1[8];
#pragma unroll
    for (int j = 0; j < 8; j++) { acc0[j] = 0.f; acc1[j] = 0.f; }
    float d0 = 0.f, d1 = 0.f;

#pragma unroll
    for (int c = 0; c < DD; c++) {
        float ks = kss[c];
        float4 kA = *(const float4*)&kvs[c][e0];
        float4 kB = *(const float4*)&kvs[c][e0 + 4];
        float q0 = qs[r][c];
        float q1 = qs[r + 32][c];
        d0 += q0 * ks; d1 += q1 * ks;
        acc0[0] += q0 * kA.x; acc0[1] += q0 * kA.y;
        acc0[2] += q0 * kA.z; acc0[3] += q0 * kA.w;
        acc0[4] += q0 * kB.x; acc0[5] += q0 * kB.y;
        acc0[6] += q0 * kB.z; acc0[7] += q0 * kB.w;
        acc1[0] += q1 * kA.x; acc1[1] += q1 * kA.y;
        acc1[2] += q1 * kA.z; acc1[3] += q1 * kA.w;
        acc1[4] += q1 * kB.x; acc1[5] += q1 * kB.y;
        acc1[6] += q1 * kB.z; acc1[7] += q1 * kB.w;
    }

    float inv0 = 1.0f / d0, inv1 = 1.0f / d1;
    float r0[8], r1[8];
#pragma unroll
    for (int j = 0; j < 8; j++) { r0[j] = acc0[j] * inv0; r1[j] = acc1[j] * inv1; }

    float* op0 = &out[((size_t)nh * SS + s0 + r) * DD + e0];
    float* op1 = &out[((size_t)nh * SS + s0 + r + 32) * DD + e0];
    *(float4*)&op0[0] = *(const float4*)&r0[0];
    *(float4*)&op0[4] = *(const float4*)&r0[4];
    *(float4*)&op1[0] = *(const float4*)&r1[0];
    *(float4*)&op1[4] = *(const float4*)&r1[4];
}

// ---------------------------------------------------------------------------
// Launch
// ---------------------------------------------------------------------------
extern "C" void kernel_launch(void* const* d_in, const int* in_sizes, int n_in,
                              void* d_out, int out_size)
{
    const float* x  = (const float*)d_in[0];
    const float* wq = (const float*)d_in[1];
    const float* bq = (const float*)d_in[2];
    const float* wk = (const float*)d_in[3];
    const float* bk = (const float*)d_in[4];
    const float* wv = (const float*)d_in[5];
    const float* bv = (const float*)d_in[6];
    float* out = (float*)d_out;

    zero_scratch<<<(NB * HH * DD * DD + 255) / 256, 256>>>();

    // bf16 hi/lo split of x and weights
    const int n4x = M_TOTAL * EE / 4;
    convert_split<<<(n4x + 255) / 256, 256>>>(x, 0, n4x);
    const int n4w = EE * EE / 4;
    convert_split<<<(n4w + 255) / 256, 256>>>(wq, 1, n4w);
    convert_split<<<(n4w + 255) / 256, 256>>>(wk, 2, n4w);
    convert_split<<<(n4w + 255) / 256, 256>>>(wv, 3, n4w);

    cudaFuncSetAttribute(qkv_gemm_mma,
                         cudaFuncAttributeMaxDynamicSharedMemorySize, SM_GEMM_TOTAL);
    dim3 ggrid(EE / 128, M_TOTAL / 128, 3);   // (8, 128, 3)
    qkv_gemm_mma<<<ggrid, 256, SM_GEMM_TOTAL>>>(bq, bk, bv);

    dim3 kvgrid(NB * HH, SPLITS);             // (64, 8)
    kv_ksum_kernel<<<kvgrid, 256>>>();

    dim3 ogrid(NB * HH, SS / 64);             // (64, 64)
    out_kernel<<<ogrid, 256>>>(out);
}

// round 6
// speedup vs baseline: 3.4821x; 1.3219x over previous
#include <cuda_runtime.h>
#include <cuda_bf16.h>
#include <cstdint>

// Problem constants (fixed by setup_inputs)
#define NB   4
#define SS   4096
#define EE   1024
#define HH   16
#define DD   64
#define EPSF 1e-3f

#define M_TOTAL (NB*SS)    // 16384

// Scratch (device globals: allocation-free)
__device__ float g_q[NB*SS*EE];     // 64 MB
__device__ float g_k[NB*SS*EE];     // 64 MB
__device__ float g_v[NB*SS*EE];     // 64 MB
__device__ float g_kv[NB*HH*DD*DD]; // 1 MB
__device__ float g_ksum[NB*HH*DD];  // 16 KB

// tf32-rounded (rna) copies of x and weights, fp32 storage
__device__ __align__(16) float g_xr[M_TOTAL*EE];  // 64 MB
__device__ __align__(16) float g_wr[3*EE*EE];     // 12 MB

#define SWZ(x) ((x) ^ (((x) >> 3) & 0x70))

// ---------------------------------------------------------------------------
// PTX helpers (portable ISA only: ldmatrix / mma.sync / cp.async)
// ---------------------------------------------------------------------------
__device__ __forceinline__ uint32_t smem_u32(const void* p) {
    uint32_t a;
    asm("{ .reg .u64 t; cvta.to.shared.u64 t, %1; cvt.u32.u64 %0, t; }"
        : "=r"(a) : "l"(p));
    return a;
}
__device__ __forceinline__ void cpa16(uint32_t dst, const void* src) {
    asm volatile("cp.async.cg.shared.global [%0], [%1], 16;"
                 :: "r"(dst), "l"(src) : "memory");
}
__device__ __forceinline__ void cpa_commit() {
    asm volatile("cp.async.commit_group;" ::: "memory");
}
template <int N>
__device__ __forceinline__ void cpa_wait() {
    asm volatile("cp.async.wait_group %0;" :: "n"(N) : "memory");
}
__device__ __forceinline__ void ldsm4(uint32_t* r, uint32_t addr) {
    asm volatile("ldmatrix.sync.aligned.m8n8.x4.shared.b16 {%0,%1,%2,%3}, [%4];"
                 : "=r"(r[0]), "=r"(r[1]), "=r"(r[2]), "=r"(r[3]) : "r"(addr));
}
__device__ __forceinline__ void mma_tf32(float* d, const uint32_t* a, const uint32_t* b) {
    asm volatile("mma.sync.aligned.m16n8k8.row.col.f32.tf32.tf32.f32 "
                 "{%0,%1,%2,%3}, {%4,%5,%6,%7}, {%8,%9}, {%0,%1,%2,%3};"
                 : "+f"(d[0]), "+f"(d[1]), "+f"(d[2]), "+f"(d[3])
                 : "r"(a[0]), "r"(a[1]), "r"(a[2]), "r"(a[3]),
                   "r"(b[0]), "r"(b[1]));
}
__device__ __forceinline__ uint32_t rna_tf32(float f) {
    uint32_t u;
    asm("cvt.rna.tf32.f32 %0, %1;" : "=r"(u) : "f"(f));
    return u;
}

// ---------------------------------------------------------------------------
// Kernel A: round fp32 -> tf32 (rna) stored as fp32.  which: 0->x, 1..3->w
// ---------------------------------------------------------------------------
__global__ void convert_rna(const float* __restrict__ src, int which, int n4)
{
    int i = blockIdx.x * blockDim.x + threadIdx.x;
    if (i >= n4) return;
    float* dst = (which == 0) ? g_xr : (g_wr + (size_t)(which - 1) * EE * EE);
    float4 v = ((const float4*)src)[i];
    uint4 o;
    o.x = rna_tf32(v.x); o.y = rna_tf32(v.y);
    o.z = rna_tf32(v.z); o.w = rna_tf32(v.w);
    ((uint4*)dst)[i] = o;
}

// ---------------------------------------------------------------------------
// Kernel B: fused QKV projection, single-pass tf32 mma.sync.
//   out[m,n] = sum_k x[m,k] * W[n,k] + bias[n]
// Tile 128x128, BK=32 fp32 (128B SW128 rows), 3-stage cp.async pipeline,
// 8 warps in 2x4 layout (warp tile 64x32), 2 CTAs/SM.
// ---------------------------------------------------------------------------
#define STAGES 3
#define STAGE_BYTES 32768       // A 16KB + B 16KB
#define SM_GEMM_TOTAL (STAGES * STAGE_BYTES)   // 98304

__global__ __launch_bounds__(256, 2) void qkv_gemm_tf32(
    const float* __restrict__ bq, const float* __restrict__ bk,
    const float* __restrict__ bv)
{
    extern __shared__ __align__(1024) char smarr[];
    const uint32_t smb = smem_u32(smarr);
    const int tid = threadIdx.x;
    const int lane = tid & 31;
    const int wid = tid >> 5;
    const int wm = wid & 1;          // 0..1
    const int wn = wid >> 1;         // 0..3
    const int z = blockIdx.z;

    const float* bias = (z == 0) ? bq : (z == 1) ? bk : bv;
    float* outp = (z == 0) ? g_q : (z == 1) ? g_k : g_v;
    const bool relu = (z != 2);
    const float* Bw = g_wr + (size_t)z * EE * EE;
    const int m0 = blockIdx.y * 128;
    const int n0 = blockIdx.x * 128;

    float acc[4][4][4];
#pragma unroll
    for (int i = 0; i < 4; i++)
#pragma unroll
        for (int j = 0; j < 4; j++)
#pragma unroll
            for (int q = 0; q < 4; q++) acc[i][j][q] = 0.f;

    // stage: A at +0 (128 rows x 128B), B at +16384
    auto load_stage = [&](int s, int kt) {
        const int k0 = kt * 32;                  // fp32 elements
        const uint32_t base = smb + s * STAGE_BYTES;
#pragma unroll
        for (int it = 0; it < 4; it++) {
            int f = tid + it * 256;              // 0..1023 segment index
            int row = f >> 3;                    // 0..127
            int seg = f & 7;                     // 16B segment in row
            uint32_t sw = SWZ((uint32_t)(row * 128 + seg * 16));
            cpa16(base + sw,         g_xr + (size_t)(m0 + row) * EE + k0 + seg * 4);
            cpa16(base + 16384 + sw, Bw   + (size_t)(n0 + row) * EE + k0 + seg * 4);
        }
    };

    load_stage(0, 0); cpa_commit();
    load_stage(1, 1); cpa_commit();

    for (int kt = 0; kt < 32; kt++) {
        cpa_wait<STAGES - 2>();
        __syncthreads();

        if (kt + STAGES - 1 < 32) load_stage((kt + STAGES - 1) % STAGES, kt + STAGES - 1);
        cpa_commit();

        const uint32_t sbA = smb + (kt % STAGES) * STAGE_BYTES;
        const uint32_t sbB = sbA + 16384;
#pragma unroll
        for (int ks = 0; ks < 4; ks++) {
            const int koff = ks * 32;            // bytes (8 fp32)
            uint32_t aF[4][4], bF[2][4];
#pragma unroll
            for (int i = 0; i < 4; i++) {
                int mr = wm * 64 + i * 16 + (lane & 15);
                uint32_t off = SWZ((uint32_t)(mr * 128 + koff + ((lane >> 4) << 4)));
                ldsm4(aF[i], sbA + off);
            }
#pragma unroll
            for (int jj = 0; jj < 2; jj++) {
                int nr = wn * 32 + jj * 16 + (lane & 7) + ((lane >> 4) << 3);
                uint32_t off = SWZ((uint32_t)(nr * 128 + koff + (((lane >> 3) & 1) << 4)));
                ldsm4(bF[jj], sbB + off);
            }
#pragma unroll
            for (int i = 0; i < 4; i++)
#pragma unroll
                for (int j = 0; j < 4; j++)
                    mma_tf32(acc[i][j], aF[i], &bF[j >> 1][(j & 1) * 2]);
        }
        __syncthreads();
    }

    // Epilogue: bias + optional relu+eps, write fp32
    const int g = lane >> 2;     // 0..7 (row in tile)
    const int tg = lane & 3;     // 0..3 (col pair)
#pragma unroll
    for (int i = 0; i < 4; i++) {
        int mbase = m0 + wm * 64 + i * 16 + g;
#pragma unroll
        for (int j = 0; j < 4; j++) {
            int n = n0 + wn * 32 + j * 8 + tg * 2;
            float b0 = __ldg(&bias[n]), b1 = __ldg(&bias[n + 1]);
            float v0 = acc[i][j][0] + b0, v1 = acc[i][j][1] + b1;
            float v2 = acc[i][j][2] + b0, v3 = acc[i][j][3] + b1;
            if (relu) {
                v0 = fmaxf(v0, 0.f) + EPSF; v1 = fmaxf(v1, 0.f) + EPSF;
                v2 = fmaxf(v2, 0.f) + EPSF; v3 = fmaxf(v3, 0.f) + EPSF;
            }
            *(float2*)&outp[(size_t)mbase * EE + n] = make_float2(v0, v1);
            *(float2*)&outp[(size_t)(mbase + 8) * EE + n] = make_float2(v2, v3);
        }
    }
}

// ---------------------------------------------------------------------------
// Kernel 0: zero kv / ksum scratch
// ---------------------------------------------------------------------------
__global__ void zero_scratch()
{
    int i = blockIdx.x * blockDim.x + threadIdx.x;
    if (i < NB * HH * DD * DD) g_kv[i] = 0.f;
    if (i < NB * HH * DD) g_ksum[i] = 0.f;
}

// ---------------------------------------------------------------------------
// Kernel 2: per-(n,h) kv = K^T V (64x64) and ksum = sum_s K[s,:].
// ---------------------------------------------------------------------------
#define SPLITS 8
#define SCHUNK 64

__global__ __launch_bounds__(256, 1) void kv_ksum_kernel()
{
    const int nh = blockIdx.x;
    const int split = blockIdx.y;
    const int n = nh >> 4, h = nh & 15;
    const float* kb = g_k + (size_t)n * SS * EE + h * DD;
    const float* vb = g_v + (size_t)n * SS * EE + h * DD;

    __shared__ float Ks[SCHUNK][DD + 4];
    __shared__ float Vs[SCHUNK][DD + 4];

    const int tid = threadIdx.x;
    const int ti = tid >> 4;
    const int tj = tid & 15;

    float acc[4][4];
#pragma unroll
    for (int a = 0; a < 4; a++)
#pragma unroll
        for (int b = 0; b < 4; b++) acc[a][b] = 0.f;
    float ksl = 0.f;

    const int sbeg = split * (SS / SPLITS);
    const int send = sbeg + (SS / SPLITS);

    for (int s0 = sbeg; s0 < send; s0 += SCHUNK) {
#pragma unroll
        for (int it = 0; it < 4; it++) {
            int f = tid + it * 256;
            int row = f >> 4;
            int c4 = (f & 15) * 4;
            float4 kv4 = *(const float4*)&kb[(size_t)(s0 + row) * EE + c4];
            Ks[row][c4 + 0] = kv4.x; Ks[row][c4 + 1] = kv4.y;
            Ks[row][c4 + 2] = kv4.z; Ks[row][c4 + 3] = kv4.w;
            float4 vv4 = *(const float4*)&vb[(size_t)(s0 + row) * EE + c4];
            Vs[row][c4 + 0] = vv4.x; Vs[row][c4 + 1] = vv4.y;
            Vs[row][c4 + 2] = vv4.z; Vs[row][c4 + 3] = vv4.w;
        }
        __syncthreads();

#pragma unroll 4
        for (int s = 0; s < SCHUNK; s++) {
            float kf[4], vf[4];
            *(float4*)&kf[0] = *(const float4*)&Ks[s][ti * 4];
            *(float4*)&vf[0] = *(const float4*)&Vs[s][tj * 4];
#pragma unroll
            for (int a = 0; a < 4; a++)
#pragma unroll
                for (int b = 0; b < 4; b++)
                    acc[a][b] += kf[a] * vf[b];
        }
        if (tid < DD) {
#pragma unroll 8
            for (int s = 0; s < SCHUNK; s++) ksl += Ks[s][tid];
        }
        __syncthreads();
    }

#pragma unroll
    for (int a = 0; a < 4; a++)
#pragma unroll
        for (int b = 0; b < 4; b++)
            atomicAdd(&g_kv[(size_t)nh * DD * DD + (ti * 4 + a) * DD + tj * 4 + b],
                      acc[a][b]);
    if (tid < DD) atomicAdd(&g_ksum[nh * DD + tid], ksl);
}

// ---------------------------------------------------------------------------
// Kernel 3: out[n,h,s,e] = (q[s,:] @ kv) / (q[s,:] . ksum)
// ---------------------------------------------------------------------------
__global__ __launch_bounds__(256, 1) void out_kernel(float* __restrict__ out)
{
    const int nh = blockIdx.x;
    const int s0 = blockIdx.y * 64;
    const int n = nh >> 4, h = nh & 15;

    __shared__ float kvs[DD][72];
    __shared__ float qs[64][72];
    __shared__ float kss[DD];

    const int tid = threadIdx.x;

    // kv tile: 64x64 = 1024 float4 -> 4 per thread
#pragma unroll
    for (int it = 0; it < 4; it++) {
        int f = tid + it * 256;
        int row = f >> 4;
        int c4 = (f & 15) * 4;
        float4 v = *(const float4*)&g_kv[(size_t)nh * DD * DD + row * DD + c4];
        *(float4*)&kvs[row][c4] = v;
    }
    if (tid < DD) kss[tid] = g_ksum[nh * DD + tid];

    const float* qb = g_q + (size_t)n * SS * EE + h * DD;
#pragma unroll
    for (int it = 0; it < 4; it++) {
        int f = tid + it * 256;
        int row = f >> 4, c4 = (f & 15) * 4;
        float4 v = *(const float4*)&qb[(size_t)(s0 + row) * EE + c4];
        *(float4*)&qs[row][c4] = v;
    }
    __syncthreads();

    const int r = tid >> 3;
    const int e0 = (tid & 7) * 8;

    float acc0[8], acc1[8];
#pragma unroll
    for (int j = 0; j < 8; j++) { acc0[j] = 0.f; acc1[j] = 0.f; }
    float d0 = 0.f, d1 = 0.f;

#pragma unroll
    for (int c = 0; c < DD; c++) {
        float ks = kss[c];
        float4 kA = *(const float4*)&kvs[c][e0];
        float4 kB = *(const float4*)&kvs[c][e0 + 4];
        float q0 = qs[r][c];
        float q1 = qs[r + 32][c];
        d0 += q0 * ks; d1 += q1 * ks;
        acc0[0] += q0 * kA.x; acc0[1] += q0 * kA.y;
        acc0[2] += q0 * kA.z; acc0[3] += q0 * kA.w;
        acc0[4] += q0 * kB.x; acc0[5] += q0 * kB.y;
        acc0[6] += q0 * kB.z; acc0[7] += q0 * kB.w;
        acc1[0] += q1 * kA.x; acc1[1] += q1 * kA.y;
        acc1[2] += q1 * kA.z; acc1[3] += q1 * kA.w;
        acc1[4] += q1 * kB.x; acc1[5] += q1 * kB.y;
        acc1[6] += q1 * kB.z; acc1[7] += q1 * kB.w;
    }

    float inv0 = 1.0f / d0, inv1 = 1.0f / d1;
    float r0[8], r1[8];
#pragma unroll
    for (int j = 0; j < 8; j++) { r0[j] = acc0[j] * inv0; r1[j] = acc1[j] * inv1; }

    float* op0 = &out[((size_t)nh * SS + s0 + r) * DD + e0];
    float* op1 = &out[((size_t)nh * SS + s0 + r + 32) * DD + e0];
    *(float4*)&op0[0] = *(const float4*)&r0[0];
    *(float4*)&op0[4] = *(const float4*)&r0[4];
    *(float4*)&op1[0] = *(const float4*)&r1[0];
    *(float4*)&op1[4] = *(const float4*)&r1[4];
}

// ---------------------------------------------------------------------------
// Launch
// ---------------------------------------------------------------------------
extern "C" void kernel_launch(void* const* d_in, const int* in_sizes, int n_in,
                              void* d_out, int out_size)
{
    const float* x  = (const float*)d_in[0];
    const float* wq = (const float*)d_in[1];
    const float* bq = (const float*)d_in[2];
    const float* wk = (const float*)d_in[3];
    const float* bk = (const float*)d_in[4];
    const float* wv = (const float*)d_in[5];
    const float* bv = (const float*)d_in[6];
    float* out = (float*)d_out;

    zero_scratch<<<(NB * HH * DD * DD + 255) / 256, 256>>>();

    // tf32 (rna) rounding of x and weights
    const int n4x = M_TOTAL * EE / 4;
    convert_rna<<<(n4x + 255) / 256, 256>>>(x, 0, n4x);
    const int n4w = EE * EE / 4;
    convert_rna<<<(n4w + 255) / 256, 256>>>(wq, 1, n4w);
    convert_rna<<<(n4w + 255) / 256, 256>>>(wk, 2, n4w);
    convert_rna<<<(n4w + 255) / 256, 256>>>(wv, 3, n4w);

    cudaFuncSetAttribute(qkv_gemm_tf32,
                         cudaFuncAttributeMaxDynamicSharedMemorySize, SM_GEMM_TOTAL);
    dim3 ggrid(EE / 128, M_TOTAL / 128, 3);   // (8, 128, 3)
    qkv_gemm_tf32<<<ggrid, 256, SM_GEMM_TOTAL>>>(bq, bk, bv);

    dim3 kvgrid(NB * HH, SPLITS);             // (64, 8)
    kv_ksum_kernel<<<kvgrid, 256>>>();

    dim3 ogrid(NB * HH, SS / 64);             // (64, 64)
    out_kernel<<<ogrid, 256>>>(out);
}